// round 8
// baseline (speedup 1.0000x reference)
#include <cuda_runtime.h>
#include <cuda_bf16.h>
#include <cstdint>

#define D 256
#define BM 128
#define BNT 64               // T tile rows (n) per iteration
#define ROWB 272             // 256 int8 + 16B pad -> conflict-free ldmatrix, 16B aligned
#define NBUF 4
#define BUFB (BNT * ROWB)    // 17408 B per T stage
#define MAXN_PAD 100032      // multiple of 64, >= 100000
#define MAXB 1024
#define NSPLIT 38            // 8 qblocks * 38 = 304 CTAs = 2/SM on 152 SMs
#define NTHREADS 256

__device__ __align__(16) signed char g_tn[(size_t)MAXN_PAD * D];   // 25.6 MB
__device__ __align__(16) signed char g_qn[(size_t)MAXB * D];
__device__ float g_st[MAXN_PAD];
__device__ float g_sq[MAXB];
__device__ float g_l[MAXB];
__device__ float g_s[MAXB];
__device__ unsigned int g_done;

// ---------------- tiny asm helpers ----------------

__device__ __forceinline__ void cp16(uint32_t dst, const void* src) {
    asm volatile("cp.async.cg.shared.global [%0], [%1], 16;" :: "r"(dst), "l"(src));
}
#define CP_COMMIT() asm volatile("cp.async.commit_group;" ::: "memory")
#define CP_WAIT2()  asm volatile("cp.async.wait_group 2;" ::: "memory")
#define CP_WAIT1()  asm volatile("cp.async.wait_group 1;" ::: "memory")
#define CP_WAIT0()  asm volatile("cp.async.wait_group 0;" ::: "memory")

__device__ __forceinline__ float fsqrt_ap(float x) {
    float r; asm("sqrt.approx.f32 %0, %1;" : "=f"(r) : "f"(x)); return r;
}
__device__ __forceinline__ float fex2_ap(float x) {
    float r; asm("ex2.approx.f32 %0, %1;" : "=f"(r) : "f"(x)); return r;
}

// ---------------- prep: L2-normalize + per-row int8 quantization ----------------
// rows [0, Npad)            -> T (g_tn, g_st)
// rows [Npad, Npad + B)     -> Q (g_qn, g_sq)

__global__ void prep_kernel(const float* __restrict__ q, const float* __restrict__ t,
                            int B, int N, int Npad) {
    int gtid = blockIdx.x * blockDim.x + threadIdx.x;
    int row  = gtid >> 5;
    int lane = threadIdx.x & 31;
    if (gtid < MAXB) { g_l[gtid] = 0.f; g_s[gtid] = 0.f; }
    if (gtid == 0) g_done = 0u;
    if (row >= Npad + B) return;

    bool isQ = (row >= Npad);
    int  r   = isQ ? (row - Npad) : row;

    if (!isQ && r >= N) {   // pad row: zeros, scale 1
        *(uint2*)(g_tn + (size_t)r * D + lane * 8) = make_uint2(0u, 0u);
        if (lane == 0) g_st[r] = 1.0f;
        return;
    }

    const float* src = (isQ ? q : t) + (size_t)r * D;
    float v[8], ss = 0.f;
#pragma unroll
    for (int i = 0; i < 8; i++) { v[i] = src[lane * 8 + i]; ss += v[i] * v[i]; }
#pragma unroll
    for (int o = 16; o > 0; o >>= 1) ss += __shfl_xor_sync(0xffffffffu, ss, o);
    float inv = 1.f / fmaxf(sqrtf(ss), 1e-12f);

    float am = 0.f;
#pragma unroll
    for (int i = 0; i < 8; i++) { v[i] *= inv; am = fmaxf(am, fabsf(v[i])); }
#pragma unroll
    for (int o = 16; o > 0; o >>= 1) am = fmaxf(am, __shfl_xor_sync(0xffffffffu, am, o));
    am = fmaxf(am, 1e-8f);
    float sc = am * (1.0f / 127.0f);
    float k  = 127.0f / am;

    int b[8];
#pragma unroll
    for (int i = 0; i < 8; i++) b[i] = __float2int_rn(v[i] * k);
    uint2 w;
    w.x = (uint32_t)(b[0] & 0xFF) | ((uint32_t)(b[1] & 0xFF) << 8) |
          ((uint32_t)(b[2] & 0xFF) << 16) | ((uint32_t)(b[3] & 0xFF) << 24);
    w.y = (uint32_t)(b[4] & 0xFF) | ((uint32_t)(b[5] & 0xFF) << 8) |
          ((uint32_t)(b[6] & 0xFF) << 16) | ((uint32_t)(b[7] & 0xFF) << 24);

    if (isQ) {
        *(uint2*)(g_qn + (size_t)r * D + lane * 8) = w;
        if (lane == 0) g_sq[r] = sc;
    } else {
        *(uint2*)(g_tn + (size_t)r * D + lane * 8) = w;
        if (lane == 0) g_st[r] = sc;
    }
}

// ---------------- main kernel ----------------
// 8 warps; warp tile 16 rows x 64 cols. A (Q, int8) in registers (32 regs).
// 4-stage cp.async T ring. s8 m16n8k32 mma, fused dequant+softmax epilogue.
// Last CTA (atomic counter) computes the final output -> no separate finalize.

__global__ __launch_bounds__(NTHREADS, 2) void knn_main_kernel(
        float* __restrict__ out, int tilesTotal, int padCount) {
    extern __shared__ unsigned char smem_raw[];
    float* stS = (float*)(smem_raw + (size_t)NBUF * BUFB);

    const int tid  = threadIdx.x;
    const int lane = tid & 31;
    const int warp = tid >> 5;
    const int wm   = warp;        // 0..7 -> 16-row slice
    const int qb   = blockIdx.x;
    const int qbase = qb * BM;

    const int t0 = (int)(((long long)blockIdx.y       * tilesTotal) / gridDim.y);
    const int t1 = (int)(((long long)(blockIdx.y + 1) * tilesTotal) / gridDim.y);
    const int cnt = t1 - t0;

    const uint32_t smemB = (uint32_t)__cvta_generic_to_shared(smem_raw);

    // ---- stage Q [128 x 256 int8] into bufs 0+1 (128*272 = 2*BUFB), load st slice ----
    {
        const uint4* src = (const uint4*)(g_qn + (size_t)qbase * D);
#pragma unroll
        for (int i = 0; i < 8; i++) {
            int idx = tid + i * NTHREADS;     // 2048 chunks of 16B
            int r = idx >> 4, c = idx & 15;
            *(uint4*)(smem_raw + r * ROWB + c * 16) = src[idx];
        }
    }
    for (int k = tid; k < cnt * BNT; k += NTHREADS) stS[k] = g_st[t0 * BNT + k];
    __syncthreads();

    // ---- hoist A fragments (int8, byte-layout == bf16 ldmatrix pattern) ----
    uint32_t Areg[8][4];
    {
        const uint32_t aBase = smemB +
            (uint32_t)((wm * 16 + (lane & 15)) * ROWB + ((lane >> 4) << 4));
#pragma unroll
        for (int ks = 0; ks < 8; ks++) {
            asm volatile("ldmatrix.sync.aligned.m8n8.x4.shared.b16 {%0,%1,%2,%3}, [%4];"
                         : "=r"(Areg[ks][0]), "=r"(Areg[ks][1]),
                           "=r"(Areg[ks][2]), "=r"(Areg[ks][3])
                         : "r"(aBase + (uint32_t)(ks * 32)));
        }
    }
    const float sq0 = g_sq[qbase + wm * 16 + (lane >> 2)];
    const float sq1 = g_sq[qbase + wm * 16 + (lane >> 2) + 8];
    const float c0 = -2.f * sq0, c1 = -2.f * sq1;
    __syncthreads();   // hoists done before T copies overwrite staging

    // ---- prologue: tiles t0, t0+1, t0+2 into bufs 0,1,2 ----
#pragma unroll
    for (int p = 0; p < 3; p++) {
        if (p < cnt) {
            const char* src = (const char*)g_tn + (size_t)(t0 + p) * BNT * D;
            const uint32_t dstB = smemB + p * BUFB;
#pragma unroll
            for (int u = 0; u < 4; u++) {
                int idx = tid + u * NTHREADS;     // 1024 chunks of 16B
                int r = idx >> 4, c = idx & 15;
                cp16(dstB + r * ROWB + c * 16, src + idx * 16);
            }
            CP_COMMIT();
        }
    }

    float lrow[2] = {0.f, 0.f}, srow[2] = {0.f, 0.f};

    const int bR  = (lane & 7) + ((lane >> 4) << 3);
    const int bCo = ((lane >> 3) & 1) << 4;
    const uint32_t bThread = (uint32_t)(bR * ROWB + bCo);

    for (int i = 0; i < cnt; i++) {
        if (i + 2 < cnt)      { CP_WAIT2(); }
        else if (i + 1 < cnt) { CP_WAIT1(); }
        else                  { CP_WAIT0(); }
        __syncthreads();   // tile i visible; all warps past buf (i+3)&3's last reads

        if (i + 3 < cnt) {   // prefetch into just-released buffer
            const char* src = (const char*)g_tn + (size_t)(t0 + i + 3) * BNT * D;
            const uint32_t dstB = smemB + ((i + 3) & 3) * BUFB;
#pragma unroll
            for (int u = 0; u < 4; u++) {
                int idx = tid + u * NTHREADS;
                int r = idx >> 4, c = idx & 15;
                cp16(dstB + r * ROWB + c * 16, src + idx * 16);
            }
            CP_COMMIT();
        }

        const uint32_t TsB = smemB + (uint32_t)((i & 3) * BUFB) + bThread;

        int acc[8][4];
#pragma unroll
        for (int nt = 0; nt < 8; nt++)
#pragma unroll
            for (int j = 0; j < 4; j++) acc[nt][j] = 0;

#pragma unroll
        for (int ks = 0; ks < 8; ks++) {
            const uint32_t kOff = (uint32_t)(ks * 32);
#pragma unroll
            for (int np = 0; np < 4; np++) {    // 16 n-rows per ldmatrix x4
                uint32_t b0, b1, b2, b3;
                uint32_t addr = TsB + (uint32_t)(np * 16 * ROWB) + kOff;
                asm volatile("ldmatrix.sync.aligned.m8n8.x4.shared.b16 {%0,%1,%2,%3}, [%4];"
                             : "=r"(b0), "=r"(b1), "=r"(b2), "=r"(b3)
                             : "r"(addr));
                asm volatile(
                    "mma.sync.aligned.m16n8k32.row.col.s32.s8.s8.s32 "
                    "{%0,%1,%2,%3}, {%4,%5,%6,%7}, {%8,%9}, {%0,%1,%2,%3};"
                    : "+r"(acc[2*np][0]), "+r"(acc[2*np][1]),
                      "+r"(acc[2*np][2]), "+r"(acc[2*np][3])
                    : "r"(Areg[ks][0]), "r"(Areg[ks][1]),
                      "r"(Areg[ks][2]), "r"(Areg[ks][3]),
                      "r"(b0), "r"(b1));
                asm volatile(
                    "mma.sync.aligned.m16n8k32.row.col.s32.s8.s8.s32 "
                    "{%0,%1,%2,%3}, {%4,%5,%6,%7}, {%8,%9}, {%0,%1,%2,%3};"
                    : "+r"(acc[2*np+1][0]), "+r"(acc[2*np+1][1]),
                      "+r"(acc[2*np+1][2]), "+r"(acc[2*np+1][3])
                    : "r"(Areg[ks][0]), "r"(Areg[ks][1]),
                      "r"(Areg[ks][2]), "r"(Areg[ks][3]),
                      "r"(b2), "r"(b3));
            }
        }

        // Fused dequant + softmax-sum epilogue (pad rows give x=2 exactly)
        const float* stP = stS + i * BNT + ((lane & 3) << 1);
#pragma unroll
        for (int nt = 0; nt < 8; nt++) {
            float2 sp = *(const float2*)(stP + nt * 8);
            float m00 = c0 * sp.x, m01 = c0 * sp.y;
            float m10 = c1 * sp.x, m11 = c1 * sp.y;
#pragma unroll
            for (int j = 0; j < 4; j++) {
                float m = (j == 0) ? m00 : (j == 1) ? m01 : (j == 2) ? m10 : m11;
                float f = __int2float_rn(acc[nt][j]);
                float x = fmaxf(fmaf(m, f, 2.f), 0.f);
                float dd = fsqrt_ap(x);
                float e  = fex2_ap(dd * -14.4269504089f);   // exp(-10*d)
                int   h  = j >> 1;
                lrow[h] += e;
                srow[h]  = fmaf(e, dd, srow[h]);
            }
        }
    }

    // lane-quad reduce, then global atomics
#pragma unroll
    for (int h = 0; h < 2; h++) {
        float lv = lrow[h], sv = srow[h];
        lv += __shfl_xor_sync(0xffffffffu, lv, 1);
        lv += __shfl_xor_sync(0xffffffffu, lv, 2);
        sv += __shfl_xor_sync(0xffffffffu, sv, 1);
        sv += __shfl_xor_sync(0xffffffffu, sv, 2);
        if ((lane & 3) == 0) {
            int r = qbase + wm * 16 + (lane >> 2) + 8 * h;
            atomicAdd(&g_l[r], lv);
            atomicAdd(&g_s[r], sv);
        }
    }

    // last CTA computes the final output
    __shared__ unsigned int lastFlag;
    __threadfence();
    if (tid == 0)
        lastFlag = (atomicAdd(&g_done, 1u) == gridDim.x * gridDim.y - 1u) ? 1u : 0u;
    __syncthreads();
    if (lastFlag) {
        float d0 = fsqrt_ap(2.0f);
        float e0 = fex2_ap(d0 * -14.4269504089f);
        float fp = (float)padCount;
        int Btot = (int)gridDim.x * BM;
        for (int iq = tid; iq < Btot; iq += NTHREADS)
            out[iq] = (g_s[iq] - fp * e0 * d0) / (g_l[iq] - fp * e0);
    }
}

// ---------------- launch ----------------

extern "C" void kernel_launch(void* const* d_in, const int* in_sizes, int n_in,
                              void* d_out, int out_size) {
    const float* q = (const float*)d_in[0];
    const float* t = (const float*)d_in[1];
    int B = in_sizes[0] / D;
    int N = in_sizes[1] / D;
    if (B > MAXB) B = MAXB;
    int Npad = ((N + BNT - 1) / BNT) * BNT;
    if (Npad > MAXN_PAD) Npad = MAXN_PAD;
    int tilesTotal = Npad / BNT;
    int padCount = tilesTotal * BNT - N;
    int maxCnt = (tilesTotal + NSPLIT - 1) / NSPLIT;

    const int smemBytes = NBUF * BUFB + maxCnt * BNT * (int)sizeof(float);
    cudaFuncSetAttribute(knn_main_kernel,
                         cudaFuncAttributeMaxDynamicSharedMemorySize, smemBytes);

    prep_kernel<<<((Npad + B) * 32 + 255) / 256, 256>>>(q, t, B, N, Npad);

    int numQB = B / BM;
    if (numQB < 1) numQB = 1;
    knn_main_kernel<<<dim3(numQB, NSPLIT), NTHREADS, smemBytes>>>(
        (float*)d_out, tilesTotal, padCount);
}

// round 10
// speedup vs baseline: 1.4240x; 1.4240x over previous
#include <cuda_runtime.h>
#include <cuda_bf16.h>
#include <cstdint>

#define D 256
#define BM 128
#define BNT 64               // T tile rows (n) per iteration
#define LDS_ROW 264          // 256 + 8 bf16 pad -> conflict-free ldmatrix
#define MAXN_PAD 100032      // multiple of 64, >= 100000
#define MAXB 1024
#define NSPLIT 38            // 8 qblocks * 38 = 304 CTAs = 2/SM on 152 SMs
#define NTHREADS 256

#define TILE_BYTES_G (BNT * D * 2)            // 32 KB contiguous per tile in gmem
#define BUF_BYTES    (BNT * LDS_ROW * 2)      // 33792 per smem buffer (padded rows)

__device__ __align__(256) __nv_bfloat16 g_tn[(size_t)MAXN_PAD * D];
__device__ __align__(256) __nv_bfloat16 g_qn[(size_t)MAXB * D];
__device__ float g_l[MAXB];
__device__ float g_s[MAXB];
__device__ unsigned int g_done;

// ---------------- tiny asm helpers ----------------

__device__ __forceinline__ void cp16(uint32_t dst, const void* src) {
    asm volatile("cp.async.cg.shared.global [%0], [%1], 16;" :: "r"(dst), "l"(src));
}
#define CP_COMMIT() asm volatile("cp.async.commit_group;" ::: "memory")
#define CP_WAIT1()  asm volatile("cp.async.wait_group 1;" ::: "memory")
#define CP_WAIT0()  asm volatile("cp.async.wait_group 0;" ::: "memory")

__device__ __forceinline__ float fsqrt_ap(float x) {
    float r; asm("sqrt.approx.f32 %0, %1;" : "=f"(r) : "f"(x)); return r;
}
__device__ __forceinline__ float fex2_ap(float x) {
    float r; asm("ex2.approx.f32 %0, %1;" : "=f"(r) : "f"(x)); return r;
}
#define LDSM4(r0, r1, r2, r3, addr) \
    asm volatile("ldmatrix.sync.aligned.m8n8.x4.shared.b16 {%0,%1,%2,%3}, [%4];" \
                 : "=r"(r0), "=r"(r1), "=r"(r2), "=r"(r3) : "r"(addr))
#define MMA16816(acc, a, b0, b1) \
    asm volatile("mma.sync.aligned.m16n8k16.row.col.f32.bf16.bf16.f32 " \
                 "{%0,%1,%2,%3}, {%4,%5,%6,%7}, {%8,%9}, {%0,%1,%2,%3};" \
                 : "+f"((acc)[0]), "+f"((acc)[1]), "+f"((acc)[2]), "+f"((acc)[3]) \
                 : "r"((a)[0]), "r"((a)[1]), "r"((a)[2]), "r"((a)[3]), \
                   "r"(b0), "r"(b1))

// ---------------- prep: L2-normalize fp32 -> bf16 (Q and T in one kernel) ----------------
// rows [0, Npad)        -> T
// rows [Npad, Npad + B) -> Q

__global__ void prep_kernel(const float* __restrict__ q, const float* __restrict__ t,
                            int B, int N, int Npad) {
    int gtid = blockIdx.x * blockDim.x + threadIdx.x;
    int row  = gtid >> 5;
    int lane = threadIdx.x & 31;
    if (gtid < MAXB) { g_l[gtid] = 0.f; g_s[gtid] = 0.f; }
    if (gtid == 0) g_done = 0u;
    if (row >= Npad + B) return;

    bool isQ = (row >= Npad);
    int  r   = isQ ? (row - Npad) : row;

    __nv_bfloat16* dst = (isQ ? g_qn : g_tn) + (size_t)r * D;

    if (!isQ && r >= N) {   // pad row: zeros
        *(uint4*)(dst + lane * 8) = make_uint4(0u, 0u, 0u, 0u);
        return;
    }

    const float* src = (isQ ? q : t) + (size_t)r * D;
    float v[8], ss = 0.f;
#pragma unroll
    for (int i = 0; i < 8; i++) { v[i] = src[lane * 8 + i]; ss += v[i] * v[i]; }
#pragma unroll
    for (int o = 16; o > 0; o >>= 1) ss += __shfl_xor_sync(0xffffffffu, ss, o);
    float inv = 1.f / fmaxf(sqrtf(ss), 1e-12f);

    uint4 w;
    uint32_t* wp = (uint32_t*)&w;
#pragma unroll
    for (int j = 0; j < 4; j++) {
        __nv_bfloat162 p = __floats2bfloat162_rn(v[2 * j] * inv, v[2 * j + 1] * inv);
        wp[j] = *(uint32_t*)&p;
    }
    *(uint4*)(dst + lane * 8) = w;
}

// ---------------- main kernel ----------------
// 8 warps; warp tile 16 rows x 64 cols. A (Q bf16) in 64 registers.
// 3-stage cp.async T ring; Q staged through bufs 0+1 then overwritten.
// B fragments software-pipelined (double-buffered ldmatrix).
// 2 CTAs/SM; last CTA computes final output.

__global__ __launch_bounds__(NTHREADS, 2) void knn_main_kernel(
        float* __restrict__ out, int tilesTotal, int padCount) {
    extern __shared__ unsigned char smem_raw[];

    const int tid  = threadIdx.x;
    const int lane = tid & 31;
    const int warp = tid >> 5;
    const int wm   = warp;        // 0..7 -> 16-row slice of 128 query rows
    const int qb   = blockIdx.x;
    const int qbase = qb * BM;

    const int t0 = (int)(((long long)blockIdx.y       * tilesTotal) / gridDim.y);
    const int t1 = (int)(((long long)(blockIdx.y + 1) * tilesTotal) / gridDim.y);
    const int cnt = t1 - t0;

    const uint32_t smemB = (uint32_t)__cvta_generic_to_shared(smem_raw);
    const uint32_t bufA[3] = { smemB, smemB + BUF_BYTES, smemB + 2u * BUF_BYTES };

    // ---- stage Q [128 x 256] into bufs 0+1, hoist A to registers ----
    {
        const uint4* src = (const uint4*)(g_qn + (size_t)qbase * D);
        __nv_bfloat16* Qs = (__nv_bfloat16*)smem_raw;
#pragma unroll
        for (int i = 0; i < 16; i++) {
            int idx = tid + i * NTHREADS;         // 4096 chunks of 16B
            int r = idx >> 5, c8 = idx & 31;
            uint4 val = src[r * 32 + c8];
            *(uint4*)(Qs + r * LDS_ROW + c8 * 8) = val;
        }
    }
    __syncthreads();

    uint32_t Areg[16][4];
    {
        const int aRow  = lane & 15;
        const int aCoff = (lane >> 4) * 8;
        const uint32_t aBase = smemB +
            (uint32_t)(((wm * 16 + aRow) * LDS_ROW + aCoff) << 1);
#pragma unroll
        for (int ks = 0; ks < 16; ks++)
            LDSM4(Areg[ks][0], Areg[ks][1], Areg[ks][2], Areg[ks][3],
                  aBase + (uint32_t)(ks * 32));
    }
    __syncthreads();   // all hoists done before T copies overwrite staging

    // ---- prologue: tiles t0 -> buf0, t0+1 -> buf1 ----
#pragma unroll
    for (int p = 0; p < 2; p++) {
        if (p < cnt) {
            const char* src = (const char*)g_tn + (size_t)(t0 + p) * TILE_BYTES_G;
#pragma unroll
            for (int i = 0; i < 8; i++) {
                int idx = tid + i * NTHREADS;     // 2048 chunks of 16B
                int r = idx >> 5, c = idx & 31;
                cp16(bufA[p] + r * (LDS_ROW * 2) + c * 16, src + r * 512 + c * 16);
            }
            CP_COMMIT();
        }
    }

    float lrow[2] = {0.f, 0.f}, srow[2] = {0.f, 0.f};

    // B ldmatrix x4 addressing: 16 n-rows per load
    const int bR = (lane & 7) + ((lane >> 4) << 3);
    const int bC = ((lane >> 3) & 1) << 3;
    const uint32_t bThread = (uint32_t)((bR * LDS_ROW + bC) << 1);

    for (int i = 0; i < cnt; i++) {
        if (i + 1 < cnt) { CP_WAIT1(); } else { CP_WAIT0(); }
        __syncthreads();   // tile i visible; all warps done with buf (i-1)%3

        // prefetch tile i+2 into the just-released buffer
        if (i + 2 < cnt) {
            const char* src = (const char*)g_tn + (size_t)(t0 + i + 2) * TILE_BYTES_G;
            const uint32_t dstB = bufA[(i + 2) % 3];
#pragma unroll
            for (int u = 0; u < 8; u++) {
                int idx = tid + u * NTHREADS;
                int r = idx >> 5, c = idx & 31;
                cp16(dstB + r * (LDS_ROW * 2) + c * 16, src + r * 512 + c * 16);
            }
            CP_COMMIT();
        }

        const uint32_t TsB = bufA[i % 3] + bThread;

        float acc[8][4];
#pragma unroll
        for (int nt = 0; nt < 8; nt++)
#pragma unroll
            for (int j = 0; j < 4; j++) acc[nt][j] = 0.f;

        // software-pipelined ldmatrix: load (ks,np)+1 before MMAs on (ks,np)
        uint32_t bq[2][4];
        LDSM4(bq[0][0], bq[0][1], bq[0][2], bq[0][3], TsB);
#pragma unroll
        for (int ks = 0; ks < 16; ks++) {
#pragma unroll
            for (int np = 0; np < 4; np++) {
                const int cur = (ks * 4 + np) & 1;
                const int nxt = cur ^ 1;
                if (!(ks == 15 && np == 3)) {
                    int nks = (np == 3) ? ks + 1 : ks;
                    int nnp = (np == 3) ? 0 : np + 1;
                    uint32_t addr = TsB + (uint32_t)(nnp * 16 * LDS_ROW * 2)
                                        + (uint32_t)(nks * 32);
                    LDSM4(bq[nxt][0], bq[nxt][1], bq[nxt][2], bq[nxt][3], addr);
                }
                MMA16816(acc[2 * np],     Areg[ks], bq[cur][0], bq[cur][1]);
                MMA16816(acc[2 * np + 1], Areg[ks], bq[cur][2], bq[cur][3]);
            }
        }

        // Fused epilogue — no masking (pad rows handled analytically below)
#pragma unroll
        for (int nt = 0; nt < 8; nt++)
#pragma unroll
            for (int j = 0; j < 4; j++) {
                float c  = acc[nt][j];
                float x  = fmaxf(fmaf(-2.f, c, 2.f), 0.f);
                float dd = fsqrt_ap(x);
                float e  = fex2_ap(dd * -14.4269504089f);   // exp(-10*d)
                int   h  = j >> 1;
                lrow[h] += e;
                srow[h]  = fmaf(e, dd, srow[h]);
            }
    }

    // lane-quad reduce; each query row owned by exactly one warp -> global atomics
#pragma unroll
    for (int h = 0; h < 2; h++) {
        float lv = lrow[h], sv = srow[h];
        lv += __shfl_xor_sync(0xffffffffu, lv, 1);
        lv += __shfl_xor_sync(0xffffffffu, lv, 2);
        sv += __shfl_xor_sync(0xffffffffu, sv, 1);
        sv += __shfl_xor_sync(0xffffffffu, sv, 2);
        if ((lane & 3) == 0) {
            int r = qbase + wm * 16 + (lane >> 2) + 8 * h;
            atomicAdd(&g_l[r], lv);
            atomicAdd(&g_s[r], sv);
        }
    }

    // last CTA computes the final output (no separate finalize launch)
    __shared__ unsigned int lastFlag;
    __threadfence();
    if (tid == 0)
        lastFlag = (atomicAdd(&g_done, 1u) == gridDim.x * gridDim.y - 1u) ? 1u : 0u;
    __syncthreads();
    if (lastFlag) {
        float d0 = fsqrt_ap(2.0f);
        float e0 = fex2_ap(d0 * -14.4269504089f);
        float fp = (float)padCount;
        int Btot = (int)gridDim.x * BM;
        for (int iq = tid; iq < Btot; iq += NTHREADS)
            out[iq] = (g_s[iq] - fp * e0 * d0) / (g_l[iq] - fp * e0);
    }
}

// ---------------- launch ----------------

extern "C" void kernel_launch(void* const* d_in, const int* in_sizes, int n_in,
                              void* d_out, int out_size) {
    const float* q = (const float*)d_in[0];
    const float* t = (const float*)d_in[1];
    int B = in_sizes[0] / D;
    int N = in_sizes[1] / D;
    if (B > MAXB) B = MAXB;
    int Npad = ((N + BNT - 1) / BNT) * BNT;
    if (Npad > MAXN_PAD) Npad = MAXN_PAD;
    int tilesTotal = Npad / BNT;
    int padCount = tilesTotal * BNT - N;

    const int smemBytes = 3 * BUF_BYTES;
    cudaFuncSetAttribute(knn_main_kernel,
                         cudaFuncAttributeMaxDynamicSharedMemorySize, smemBytes);

    prep_kernel<<<((Npad + B) * 32 + 255) / 256, 256>>>(q, t, B, N, Npad);

    int numQB = B / BM;
    if (numQB < 1) numQB = 1;
    knn_main_kernel<<<dim3(numQB, NSPLIT), NTHREADS, smemBytes>>>(
        (float*)d_out, tilesTotal, padCount);
}

// round 11
// speedup vs baseline: 2.1668x; 1.5216x over previous
#include <cuda_runtime.h>
#include <cuda_bf16.h>
#include <cstdint>

#define D 256
#define BM 128
#define BNT 64               // T tile rows (n) per iteration
#define LDS_ROW 264          // 256 + 8 bf16 pad -> conflict-free ldmatrix
#define MAXN_PAD 100032      // multiple of 64, >= 100000
#define MAXB 1024
#define NSPLIT 38            // 8 qblocks * 38 = 304 CTAs = 2/SM on 152 SMs
#define NTHREADS 256

#define TILE_BYTES_G (BNT * D * 2)            // 32 KB contiguous per tile in gmem
#define BUF_BYTES    (BNT * LDS_ROW * 2)      // 33792 per smem buffer (padded rows)

__device__ __align__(256) __nv_bfloat16 g_tn[(size_t)MAXN_PAD * D];
__device__ __align__(256) __nv_bfloat16 g_qn[(size_t)MAXB * D];
__device__ float g_l[MAXB];
__device__ float g_s[MAXB];
__device__ unsigned int g_done;

// ---------------- tiny asm helpers ----------------

__device__ __forceinline__ void cp16(uint32_t dst, const void* src) {
    asm volatile("cp.async.cg.shared.global [%0], [%1], 16;" :: "r"(dst), "l"(src));
}
#define CP_COMMIT() asm volatile("cp.async.commit_group;" ::: "memory")
#define CP_WAIT1()  asm volatile("cp.async.wait_group 1;" ::: "memory")
#define CP_WAIT0()  asm volatile("cp.async.wait_group 0;" ::: "memory")

__device__ __forceinline__ float fsqrt_ap(float x) {
    float r; asm("sqrt.approx.f32 %0, %1;" : "=f"(r) : "f"(x)); return r;
}
__device__ __forceinline__ float fex2_ap(float x) {
    float r; asm("ex2.approx.f32 %0, %1;" : "=f"(r) : "f"(x)); return r;
}
#define LDSM4(r0, r1, r2, r3, addr) \
    asm volatile("ldmatrix.sync.aligned.m8n8.x4.shared.b16 {%0,%1,%2,%3}, [%4];" \
                 : "=r"(r0), "=r"(r1), "=r"(r2), "=r"(r3) : "r"(addr))
#define MMA16816(acc, a, b0, b1) \
    asm volatile("mma.sync.aligned.m16n8k16.row.col.f32.bf16.bf16.f32 " \
                 "{%0,%1,%2,%3}, {%4,%5,%6,%7}, {%8,%9}, {%0,%1,%2,%3};" \
                 : "+f"((acc)[0]), "+f"((acc)[1]), "+f"((acc)[2]), "+f"((acc)[3]) \
                 : "r"((a)[0]), "r"((a)[1]), "r"((a)[2]), "r"((a)[3]), \
                   "r"(b0), "r"(b1))

// ---------------- prep: L2-normalize fp32 -> bf16 (Q and T in one kernel) ----------------
// rows [0, Npad)        -> T
// rows [Npad, Npad + B) -> Q

__global__ void prep_kernel(const float* __restrict__ q, const float* __restrict__ t,
                            int B, int N, int Npad) {
    int gtid = blockIdx.x * blockDim.x + threadIdx.x;
    int row  = gtid >> 5;
    int lane = threadIdx.x & 31;
    if (gtid < MAXB) { g_l[gtid] = 0.f; g_s[gtid] = 0.f; }
    if (gtid == 0) g_done = 0u;
    if (row >= Npad + B) return;

    bool isQ = (row >= Npad);
    int  r   = isQ ? (row - Npad) : row;

    __nv_bfloat16* dst = (isQ ? g_qn : g_tn) + (size_t)r * D;

    if (!isQ && r >= N) {   // pad row: zeros
        *(uint4*)(dst + lane * 8) = make_uint4(0u, 0u, 0u, 0u);
        return;
    }

    const float4* src = (const float4*)((isQ ? q : t) + (size_t)r * D) + lane * 2;
    float4 v0 = src[0];
    float4 v1 = src[1];
    float ss = v0.x * v0.x + v0.y * v0.y + v0.z * v0.z + v0.w * v0.w
             + v1.x * v1.x + v1.y * v1.y + v1.z * v1.z + v1.w * v1.w;
#pragma unroll
    for (int o = 16; o > 0; o >>= 1) ss += __shfl_xor_sync(0xffffffffu, ss, o);
    float inv = 1.f / fmaxf(sqrtf(ss), 1e-12f);

    uint4 w;
    uint32_t* wp = (uint32_t*)&w;
    __nv_bfloat162 p0 = __floats2bfloat162_rn(v0.x * inv, v0.y * inv);
    __nv_bfloat162 p1 = __floats2bfloat162_rn(v0.z * inv, v0.w * inv);
    __nv_bfloat162 p2 = __floats2bfloat162_rn(v1.x * inv, v1.y * inv);
    __nv_bfloat162 p3 = __floats2bfloat162_rn(v1.z * inv, v1.w * inv);
    wp[0] = *(uint32_t*)&p0;
    wp[1] = *(uint32_t*)&p1;
    wp[2] = *(uint32_t*)&p2;
    wp[3] = *(uint32_t*)&p3;
    *(uint4*)(dst + lane * 8) = w;
}

// ---------------- main kernel ----------------
// 8 warps; warp tile 16 rows x 64 cols. A (Q bf16) in 64 registers.
// 3-stage cp.async T ring; Q staged through bufs 0+1 then overwritten.
// 2 CTAs/SM; last CTA computes final output. (Inner loop = R6's, best measured.)

__global__ __launch_bounds__(NTHREADS, 2) void knn_main_kernel(
        float* __restrict__ out, int tilesTotal, int padCount) {
    extern __shared__ unsigned char smem_raw[];

    const int tid  = threadIdx.x;
    const int lane = tid & 31;
    const int warp = tid >> 5;
    const int wm   = warp;        // 0..7 -> 16-row slice of 128 query rows
    const int qb   = blockIdx.x;
    const int qbase = qb * BM;

    const int t0 = (int)(((long long)blockIdx.y       * tilesTotal) / gridDim.y);
    const int t1 = (int)(((long long)(blockIdx.y + 1) * tilesTotal) / gridDim.y);
    const int cnt = t1 - t0;

    const uint32_t smemB = (uint32_t)__cvta_generic_to_shared(smem_raw);
    const uint32_t bufA[3] = { smemB, smemB + BUF_BYTES, smemB + 2u * BUF_BYTES };

    // ---- stage Q [128 x 256] into bufs 0+1, hoist A to registers ----
    {
        const uint4* src = (const uint4*)(g_qn + (size_t)qbase * D);
        __nv_bfloat16* Qs = (__nv_bfloat16*)smem_raw;
#pragma unroll
        for (int i = 0; i < 16; i++) {
            int idx = tid + i * NTHREADS;         // 4096 chunks of 16B
            int r = idx >> 5, c8 = idx & 31;
            uint4 val = src[r * 32 + c8];
            *(uint4*)(Qs + r * LDS_ROW + c8 * 8) = val;
        }
    }
    __syncthreads();

    uint32_t Areg[16][4];
    {
        const int aRow  = lane & 15;
        const int aCoff = (lane >> 4) * 8;
        const uint32_t aBase = smemB +
            (uint32_t)(((wm * 16 + aRow) * LDS_ROW + aCoff) << 1);
#pragma unroll
        for (int ks = 0; ks < 16; ks++)
            LDSM4(Areg[ks][0], Areg[ks][1], Areg[ks][2], Areg[ks][3],
                  aBase + (uint32_t)(ks * 32));
    }
    __syncthreads();   // all hoists done before T copies overwrite staging

    // ---- prologue: tiles t0 -> buf0, t0+1 -> buf1 ----
#pragma unroll
    for (int p = 0; p < 2; p++) {
        if (p < cnt) {
            const char* src = (const char*)g_tn + (size_t)(t0 + p) * TILE_BYTES_G;
#pragma unroll
            for (int i = 0; i < 8; i++) {
                int idx = tid + i * NTHREADS;     // 2048 chunks of 16B
                int r = idx >> 5, c = idx & 31;
                cp16(bufA[p] + r * (LDS_ROW * 2) + c * 16, src + r * 512 + c * 16);
            }
            CP_COMMIT();
        }
    }

    float lrow[2] = {0.f, 0.f}, srow[2] = {0.f, 0.f};

    // B ldmatrix x4 addressing: 16 n-rows per load
    const int bR = (lane & 7) + ((lane >> 4) << 3);
    const int bC = ((lane >> 3) & 1) << 3;
    const uint32_t bThread = (uint32_t)((bR * LDS_ROW + bC) << 1);

    for (int i = 0; i < cnt; i++) {
        if (i + 1 < cnt) { CP_WAIT1(); } else { CP_WAIT0(); }
        __syncthreads();   // tile i visible; all warps done with buf (i-1)%3

        // prefetch tile i+2 into the just-released buffer
        if (i + 2 < cnt) {
            const char* src = (const char*)g_tn + (size_t)(t0 + i + 2) * TILE_BYTES_G;
            const uint32_t dstB = bufA[(i + 2) % 3];
#pragma unroll
            for (int u = 0; u < 8; u++) {
                int idx = tid + u * NTHREADS;
                int r = idx >> 5, c = idx & 31;
                cp16(dstB + r * (LDS_ROW * 2) + c * 16, src + r * 512 + c * 16);
            }
            CP_COMMIT();
        }

        const uint32_t TsB = bufA[i % 3] + bThread;

        float acc[8][4];
#pragma unroll
        for (int nt = 0; nt < 8; nt++)
#pragma unroll
            for (int j = 0; j < 4; j++) acc[nt][j] = 0.f;

#pragma unroll
        for (int ks = 0; ks < 16; ks++) {
            const uint32_t kOff = (uint32_t)(ks * 32);
#pragma unroll
            for (int np = 0; np < 4; np++) {    // 16 n-rows per ldmatrix x4
                uint32_t b0, b1, b2, b3;
                uint32_t addr = TsB + (uint32_t)(np * 16 * LDS_ROW * 2) + kOff;
                LDSM4(b0, b1, b2, b3, addr);
                MMA16816(acc[2 * np],     Areg[ks], b0, b1);
                MMA16816(acc[2 * np + 1], Areg[ks], b2, b3);
            }
        }

        // Fused epilogue — no masking (pad rows handled analytically below)
#pragma unroll
        for (int nt = 0; nt < 8; nt++)
#pragma unroll
            for (int j = 0; j < 4; j++) {
                float c  = acc[nt][j];
                float x  = fmaxf(fmaf(-2.f, c, 2.f), 0.f);
                float dd = fsqrt_ap(x);
                float e  = fex2_ap(dd * -14.4269504089f);   // exp(-10*d)
                int   h  = j >> 1;
                lrow[h] += e;
                srow[h]  = fmaf(e, dd, srow[h]);
            }
    }

    // lane-quad reduce; each query row owned by exactly one warp -> global atomics
#pragma unroll
    for (int h = 0; h < 2; h++) {
        float lv = lrow[h], sv = srow[h];
        lv += __shfl_xor_sync(0xffffffffu, lv, 1);
        lv += __shfl_xor_sync(0xffffffffu, lv, 2);
        sv += __shfl_xor_sync(0xffffffffu, sv, 1);
        sv += __shfl_xor_sync(0xffffffffu, sv, 2);
        if ((lane & 3) == 0) {
            int r = qbase + wm * 16 + (lane >> 2) + 8 * h;
            atomicAdd(&g_l[r], lv);
            atomicAdd(&g_s[r], sv);
        }
    }

    // last CTA computes the final output (no separate finalize launch)
    __shared__ unsigned int lastFlag;
    __threadfence();
    if (tid == 0)
        lastFlag = (atomicAdd(&g_done, 1u) == gridDim.x * gridDim.y - 1u) ? 1u : 0u;
    __syncthreads();
    if (lastFlag) {
        __threadfence();
        float d0 = fsqrt_ap(2.0f);
        float e0 = fex2_ap(d0 * -14.4269504089f);
        float fp = (float)padCount;
        int Btot = (int)gridDim.x * BM;
        for (int iq = tid; iq < Btot; iq += NTHREADS)
            out[iq] = (g_s[iq] - fp * e0 * d0) / (g_l[iq] - fp * e0);
    }
}

// ---------------- launch ----------------

extern "C" void kernel_launch(void* const* d_in, const int* in_sizes, int n_in,
                              void* d_out, int out_size) {
    const float* q = (const float*)d_in[0];
    const float* t = (const float*)d_in[1];
    int B = in_sizes[0] / D;
    int N = in_sizes[1] / D;
    if (B > MAXB) B = MAXB;
    int Npad = ((N + BNT - 1) / BNT) * BNT;
    if (Npad > MAXN_PAD) Npad = MAXN_PAD;
    int tilesTotal = Npad / BNT;
    int padCount = tilesTotal * BNT - N;

    const int smemBytes = 3 * BUF_BYTES;
    cudaFuncSetAttribute(knn_main_kernel,
                         cudaFuncAttributeMaxDynamicSharedMemorySize, smemBytes);

    prep_kernel<<<((Npad + B) * 32 + 255) / 256, 256>>>(q, t, B, N, Npad);

    int numQB = B / BM;
    if (numQB < 1) numQB = 1;
    knn_main_kernel<<<dim3(numQB, NSPLIT), NTHREADS, smemBytes>>>(
        (float*)d_out, tilesTotal, padCount);
}